// round 7
// baseline (speedup 1.0000x reference)
#include <cuda_runtime.h>
#include <cuda_bf16.h>
#include <cstddef>

// ---------------------------------------------------------------------------
// GRU (B=64, N=1024, T=512), exact fp32, packed f32x2 FMA.
//
// Graph = 4 kernel nodes total (the R5 failure was a 2MB driver graph-upload
// pool retained for a 1025-node graph; the recurrence is now ONE persistent
// kernel with a software grid barrier).
//
// Phase 1:  XP[b*T+t, 0:3072] = x_{b,t} @ [W1|W2] + [b1|b2]   (one GEMM kernel)
// Phase 2:  persistent kernel, 512 steps:
//             each of 128 blocks: 64x96 partial of h @ Wc over 256 k's
//             grid barrier -> fused split-K reduce + gates + h update
//             grid barrier
// ---------------------------------------------------------------------------

#define Bsz 64
#define Nn  1024
#define Tt  512
#define N3  3072
#define Kd  1024

#define NB      128    // persistent blocks (<= 148 SMs, co-resident)
#define CTILES  32     // column tiles of 96
#define KSPLIT  4      // k splits of 256
#define CP      96     // cols per block
#define KRANGE  256    // k per block
#define KC      64     // k chunk in smem

typedef unsigned long long ull;

__device__ __forceinline__ ull pk2(float lo, float hi) {
    ull r; asm("mov.b64 %0, {%1,%2};" : "=l"(r) : "f"(lo), "f"(hi)); return r;
}
__device__ __forceinline__ void upk2(ull v, float& lo, float& hi) {
    asm("mov.b64 {%0,%1}, %2;" : "=f"(lo), "=f"(hi) : "l"(v));
}
__device__ __forceinline__ void ffma2(ull& d, ull a, ull b) {
    asm("fma.rn.f32x2 %0, %1, %2, %0;" : "+l"(d) : "l"(a), "l"(b));
}

// ------------------------- device scratch ----------------------------------
__device__ float g_Wc[(size_t)Kd * N3];              // 12 MB packed [W1|W2]
__device__ float g_bc[N3];
__device__ float g_XP[(size_t)Bsz * Tt * N3];        // 402 MB input projections
__device__ float g_H[Bsz * Nn];
__device__ float g_G[(size_t)KSPLIT * Bsz * N3];     // 3 MB split-K partials

__device__ volatile unsigned g_bar_gen;
__device__ unsigned g_bar_cnt;

// ------------------------- init / pack -------------------------------------
__global__ void pack_w(const float* __restrict__ W1, const float* __restrict__ b1,
                       const float* __restrict__ W2, const float* __restrict__ b2) {
    int idx = blockIdx.x * 256 + threadIdx.x;
    if (idx < Kd * N3) {
        int k = idx / N3, j = idx - k * N3;
        g_Wc[idx] = (j < 2048) ? W1[k * 2048 + j] : W2[k * 1024 + (j - 2048)];
    }
    if (idx < N3) g_bc[idx] = (idx < 2048) ? b1[idx] : b2[idx - 2048];
}

__global__ void init_state() {
    int i = blockIdx.x * 256 + threadIdx.x;
    if (i < Bsz * Nn) g_H[i] = 0.f;
    if (i == 0) { g_bar_cnt = 0; g_bar_gen = 0; }
}

// ------------------------- phase 1: input projection ------------------------
// C[32768, 3072] = A[32768,1024] * Wc + bc.  BM=BN=128, BK=8, 8x8/thread.
__global__ __launch_bounds__(256) void xproj(const float* __restrict__ fx) {
    __shared__ float As[8][128];
    __shared__ float Bs[8][128];

    const int tid = threadIdx.x;
    const int jb  = blockIdx.x * 128;
    const int m0  = blockIdx.y * 128;
    const int b   = m0 >> 9;
    const int t0  = m0 & 511;
    const float* Abase = fx + ((size_t)b * Kd) * Tt + t0;

    const int kk = tid >> 5, lane = tid & 31;
    const int ty = tid >> 4, tx = tid & 15;

    ull acc[8][4];
#pragma unroll
    for (int r = 0; r < 8; r++)
#pragma unroll
        for (int c = 0; c < 4; c++) acc[r][c] = 0ull;

    for (int k0 = 0; k0 < Kd; k0 += 8) {
        const float* ap = Abase + (size_t)(k0 + kk) * Tt;
        As[kk][lane]      = ap[lane];
        As[kk][lane + 32] = ap[lane + 32];
        As[kk][lane + 64] = ap[lane + 64];
        As[kk][lane + 96] = ap[lane + 96];
        *(float4*)&Bs[kk][lane * 4] =
            *(const float4*)(g_Wc + (size_t)(k0 + kk) * N3 + jb + lane * 4);
        __syncthreads();

#pragma unroll
        for (int q = 0; q < 8; q++) {
            const float4 a0 = *(const float4*)&As[q][ty * 8];
            const float4 a1 = *(const float4*)&As[q][ty * 8 + 4];
            const ull* bv = (const ull*)&Bs[q][tx * 8];
            const ull b0 = bv[0], b1v = bv[1], b2v = bv[2], b3v = bv[3];
            float ar[8] = {a0.x, a0.y, a0.z, a0.w, a1.x, a1.y, a1.z, a1.w};
#pragma unroll
            for (int r = 0; r < 8; r++) {
                ull aa = pk2(ar[r], ar[r]);
                ffma2(acc[r][0], aa, b0);
                ffma2(acc[r][1], aa, b1v);
                ffma2(acc[r][2], aa, b2v);
                ffma2(acc[r][3], aa, b3v);
            }
        }
        __syncthreads();
    }

    float bb[8];
#pragma unroll
    for (int c = 0; c < 8; c++) bb[c] = g_bc[jb + tx * 8 + c];

#pragma unroll
    for (int r = 0; r < 8; r++) {
        float* op = g_XP + (size_t)(m0 + ty * 8 + r) * N3 + jb + tx * 8;
        float4 v0, v1;
        upk2(acc[r][0], v0.x, v0.y); upk2(acc[r][1], v0.z, v0.w);
        upk2(acc[r][2], v1.x, v1.y); upk2(acc[r][3], v1.z, v1.w);
        v0.x += bb[0]; v0.y += bb[1]; v0.z += bb[2]; v0.w += bb[3];
        v1.x += bb[4]; v1.y += bb[5]; v1.z += bb[6]; v1.w += bb[7];
        *(float4*)&op[0] = v0;
        *(float4*)&op[4] = v1;
    }
}

// ------------------------- grid barrier ------------------------------------
__device__ __forceinline__ void grid_sync() {
    __syncthreads();
    if (threadIdx.x == 0) {
        unsigned gen = g_bar_gen;
        __threadfence();
        if (atomicAdd(&g_bar_cnt, 1u) == NB - 1) {
            g_bar_cnt = 0;
            __threadfence();
            g_bar_gen = gen + 1;
        } else {
            while (g_bar_gen == gen) { __nanosleep(64); }
        }
        __threadfence();
    }
    __syncthreads();
}

// ------------------------- phase 2: persistent recurrence -------------------
__global__ __launch_bounds__(256) void recurrence(const float* __restrict__ b1,
                                                  const float* __restrict__ b2,
                                                  float* __restrict__ out) {
    __shared__ float h_s[64][68];      // pad 4: 16B-aligned rows, conflict-free
    __shared__ float w_s[KC][CP];

    const int tid = threadIdx.x;
    const int blk = blockIdx.x;
    const int ct  = blk & (CTILES - 1);     // column tile 0..31
    const int sk  = blk >> 5;               // k split 0..3
    const int jb  = ct * CP;
    const int kbase = sk * KRANGE;
    const int rg = tid >> 4;                // rows rg*4 .. +3
    const int cg = tid & 15;                // cols cg*6 .. +5

    for (int t = 0; t < Tt; t++) {
        ull acc[4][3];
#pragma unroll
        for (int i = 0; i < 4; i++) { acc[i][0] = 0ull; acc[i][1] = 0ull; acc[i][2] = 0ull; }

        for (int k0 = kbase; k0 < kbase + KRANGE; k0 += KC) {
            // h tile: 64 x 64 floats = 1024 float4
#pragma unroll
            for (int i = 0; i < 4; i++) {
                int li = tid + i * 256;
                int r = li >> 4, c4 = li & 15;
                *(float4*)&h_s[r][c4 * 4] =
                    *(const float4*)&g_H[r * Nn + k0 + c4 * 4];
            }
            // W tile: 64 x 96 floats = 1536 float4
#pragma unroll
            for (int i = 0; i < 6; i++) {
                int li = tid + i * 256;
                int r = li / 24, c4 = li % 24;
                *(float4*)&w_s[r][c4 * 4] =
                    *(const float4*)(g_Wc + (size_t)(k0 + r) * N3 + jb + c4 * 4);
            }
            __syncthreads();

#pragma unroll
            for (int kk = 0; kk < KC; kk++) {
                const ull* wv = (const ull*)&w_s[kk][cg * 6];
                const ull w0 = wv[0], w1 = wv[1], w2 = wv[2];
#pragma unroll
                for (int i = 0; i < 4; i++) {
                    float a = h_s[rg * 4 + i][kk];
                    ull aa = pk2(a, a);
                    ffma2(acc[i][0], aa, w0);
                    ffma2(acc[i][1], aa, w1);
                    ffma2(acc[i][2], aa, w2);
                }
            }
            __syncthreads();
        }

        // store split-K partials: g_G[(sk*64 + row)*N3 + col]
#pragma unroll
        for (int i = 0; i < 4; i++) {
            ull* gp = (ull*)(g_G + ((size_t)(sk * 64 + rg * 4 + i)) * N3 + jb + cg * 6);
            gp[0] = acc[i][0]; gp[1] = acc[i][1]; gp[2] = acc[i][2];
        }

        grid_sync();

        // fused reduce + gates + h update: 2 elements per thread
#pragma unroll
        for (int e = 0; e < 2; e++) {
            int idx = blk * 512 + e * 256 + tid;      // 0..65535
            int m = idx >> 10, n = idx & 1023;
            // reference adds biases in BOTH x-proj and h-proj — replicate
            float h1 = b1[n], h2 = b1[1024 + n], hh = b2[n];
#pragma unroll
            for (int ss = 0; ss < KSPLIT; ss++) {
                const float* gp = g_G + ((size_t)(ss * 64 + m)) * N3;
                h1 += gp[n]; h2 += gp[1024 + n]; hh += gp[2048 + n];
            }
            const float* xp = g_XP + ((size_t)(m * Tt + t)) * N3;
            float x1 = xp[n], x2 = xp[1024 + n], xh = xp[2048 + n];

            float z = 1.f / (1.f + expf(-(x1 + h1)));
            float r = 1.f / (1.f + expf(-(x2 + h2)));
            float hn = z * g_H[idx] + (1.f - z) * tanhf(xh + r * hh);
            g_H[idx] = hn;
            if (t == Tt - 1) out[idx] = hn;
        }

        grid_sync();
    }
}

// ---------------------------------------------------------------------------
extern "C" void kernel_launch(void* const* d_in, const int* in_sizes, int n_in,
                              void* d_out, int out_size) {
    const float *fx = nullptr, *W1 = nullptr, *b1 = nullptr, *W2 = nullptr, *b2 = nullptr;
    for (int i = 0; i < n_in; i++) {
        switch (in_sizes[i]) {
            case Bsz * Nn * Tt:  fx = (const float*)d_in[i]; break;
            case Nn * 2 * Nn:    W1 = (const float*)d_in[i]; break;
            case 2 * Nn:         b1 = (const float*)d_in[i]; break;
            case Nn * Nn:        W2 = (const float*)d_in[i]; break;
            case Nn:             b2 = (const float*)d_in[i]; break;
            default: break;
        }
    }
    float* out = (float*)d_out;

    pack_w<<<(Kd * N3 + 255) / 256, 256>>>(W1, b1, W2, b2);
    init_state<<<(Bsz * Nn + 255) / 256, 256>>>();

    dim3 g1(N3 / 128, (Bsz * Tt) / 128);   // (24, 256)
    xproj<<<g1, 256>>>(fx);

    recurrence<<<NB, 256>>>(b1, b2, out);
}

// round 8
// speedup vs baseline: 1.0738x; 1.0738x over previous
#include <cuda_runtime.h>
#include <cuda_bf16.h>
#include <cstddef>

// ---------------------------------------------------------------------------
// GRU (B=64, N=1024, T=512), exact fp32, packed f32x2 FMA.
//
// Phase 1:  XP[b*T+t, 0:3072] = x_{b,t} @ [W1|W2] + [b1|b2]   (one GEMM)
// Phase 2:  ONE persistent kernel, 512 steps, ONE grid barrier per step:
//   - 128 blocks; block owns 8 gate-columns (24 GEMM cols), FULL K=1024
//   - W slice resident in smem for all 512 steps (96 KB)
//   - h double-buffered in global, stored TRANSPOSED [k][m] for coalesced,
//     conflict-free reload into a transposed smem tile
//   - in-block 4-way K-split (one 64-thread group per split), smem reduce,
//     fused gating update writes h[next] — all block-local
// ---------------------------------------------------------------------------

#define Bsz 64
#define Nn  1024
#define Tt  512
#define N3  3072
#define Kd  1024
#define NB  128          // persistent blocks, 1/SM, co-resident

typedef unsigned long long ull;

__device__ __forceinline__ ull pk2(float lo, float hi) {
    ull r; asm("mov.b64 %0, {%1,%2};" : "=l"(r) : "f"(lo), "f"(hi)); return r;
}
__device__ __forceinline__ void upk2(ull v, float& lo, float& hi) {
    asm("mov.b64 {%0,%1}, %2;" : "=f"(lo), "=f"(hi) : "l"(v));
}
__device__ __forceinline__ void ffma2(ull& d, ull a, ull b) {
    asm("fma.rn.f32x2 %0, %1, %2, %0;" : "+l"(d) : "l"(a), "l"(b));
}

// ------------------------- device scratch ----------------------------------
__device__ float g_Wc[(size_t)Kd * N3];          // 12 MB packed [W1|W2] (xproj)
__device__ float g_bc[N3];
__device__ float g_XP[(size_t)Bsz * Tt * N3];    // 402 MB input projections
__device__ float g_Ht[2][(size_t)Nn * Bsz];      // h, TRANSPOSED [k][m], 2 buffers

__device__ volatile unsigned g_bar_gen;
__device__ unsigned g_bar_cnt;

// ------------------------- init / pack -------------------------------------
__global__ void pack_w(const float* __restrict__ W1, const float* __restrict__ b1,
                       const float* __restrict__ W2, const float* __restrict__ b2) {
    int idx = blockIdx.x * 256 + threadIdx.x;
    if (idx < Kd * N3) {
        int k = idx / N3, j = idx - k * N3;
        g_Wc[idx] = (j < 2048) ? W1[k * 2048 + j] : W2[k * 1024 + (j - 2048)];
    }
    if (idx < N3) g_bc[idx] = (idx < 2048) ? b1[idx] : b2[idx - 2048];
}

__global__ void init_state() {
    int i = blockIdx.x * 256 + threadIdx.x;
    if (i < Nn * Bsz) g_Ht[0][i] = 0.f;
    if (i == 0) { g_bar_cnt = 0; g_bar_gen = 0; }
}

// ------------------------- phase 1: input projection ------------------------
__global__ __launch_bounds__(256) void xproj(const float* __restrict__ fx) {
    __shared__ float As[8][128];
    __shared__ float Bs[8][128];

    const int tid = threadIdx.x;
    const int jb  = blockIdx.x * 128;
    const int m0  = blockIdx.y * 128;
    const int b   = m0 >> 9;
    const int t0  = m0 & 511;
    const float* Abase = fx + ((size_t)b * Kd) * Tt + t0;

    const int kk = tid >> 5, lane = tid & 31;
    const int ty = tid >> 4, tx = tid & 15;

    ull acc[8][4];
#pragma unroll
    for (int r = 0; r < 8; r++)
#pragma unroll
        for (int c = 0; c < 4; c++) acc[r][c] = 0ull;

    for (int k0 = 0; k0 < Kd; k0 += 8) {
        const float* ap = Abase + (size_t)(k0 + kk) * Tt;
        As[kk][lane]      = ap[lane];
        As[kk][lane + 32] = ap[lane + 32];
        As[kk][lane + 64] = ap[lane + 64];
        As[kk][lane + 96] = ap[lane + 96];
        *(float4*)&Bs[kk][lane * 4] =
            *(const float4*)(g_Wc + (size_t)(k0 + kk) * N3 + jb + lane * 4);
        __syncthreads();

#pragma unroll
        for (int q = 0; q < 8; q++) {
            const float4 a0 = *(const float4*)&As[q][ty * 8];
            const float4 a1 = *(const float4*)&As[q][ty * 8 + 4];
            const ull* bv = (const ull*)&Bs[q][tx * 8];
            const ull b0 = bv[0], b1v = bv[1], b2v = bv[2], b3v = bv[3];
            float ar[8] = {a0.x, a0.y, a0.z, a0.w, a1.x, a1.y, a1.z, a1.w};
#pragma unroll
            for (int r = 0; r < 8; r++) {
                ull aa = pk2(ar[r], ar[r]);
                ffma2(acc[r][0], aa, b0);
                ffma2(acc[r][1], aa, b1v);
                ffma2(acc[r][2], aa, b2v);
                ffma2(acc[r][3], aa, b3v);
            }
        }
        __syncthreads();
    }

    float bb[8];
#pragma unroll
    for (int c = 0; c < 8; c++) bb[c] = g_bc[jb + tx * 8 + c];

#pragma unroll
    for (int r = 0; r < 8; r++) {
        float* op = g_XP + (size_t)(m0 + ty * 8 + r) * N3 + jb + tx * 8;
        float4 v0, v1;
        upk2(acc[r][0], v0.x, v0.y); upk2(acc[r][1], v0.z, v0.w);
        upk2(acc[r][2], v1.x, v1.y); upk2(acc[r][3], v1.z, v1.w);
        v0.x += bb[0]; v0.y += bb[1]; v0.z += bb[2]; v0.w += bb[3];
        v1.x += bb[4]; v1.y += bb[5]; v1.z += bb[6]; v1.w += bb[7];
        *(float4*)&op[0] = v0;
        *(float4*)&op[4] = v1;
    }
}

// ------------------------- phase 2: persistent recurrence -------------------
// smem layout (floats):
//   w_s   [1024][24]        98304 B   W slice, resident across all steps
//   hT_s  [4][64][64]       65536 B   transposed h chunk (per k-split group)
//   p_s   [4][64][26]       26624 B   in-block K-split partials (pad 26)
//   bias_s[24]                 96 B
#define SM_W   (1024 * 24)
#define SM_HT  (4 * 64 * 64)
#define SM_P   (4 * 64 * 26)
#define SM_TOT ((SM_W + SM_HT + SM_P + 24) * 4)

__device__ __forceinline__ void grid_sync() {
    __syncthreads();
    if (threadIdx.x == 0) {
        unsigned gen = g_bar_gen;
        __threadfence();
        if (atomicAdd(&g_bar_cnt, 1u) == NB - 1) {
            g_bar_cnt = 0;
            __threadfence();
            g_bar_gen = gen + 1;
        } else {
            while (g_bar_gen == gen) { __nanosleep(64); }
        }
        __threadfence();
    }
    __syncthreads();
}

__global__ __launch_bounds__(256, 1) void recurrence(
        const float* __restrict__ W1, const float* __restrict__ W2,
        const float* __restrict__ b1, const float* __restrict__ b2,
        float* __restrict__ out) {
    extern __shared__ float smem[];
    float* w_s    = smem;                 // [k][24]
    float* hT_s   = w_s + SM_W;           // [g][64][64]
    float* p_s    = hT_s + SM_HT;         // [g][64][26]
    float* bias_s = p_s + SM_P;           // [24]

    const int tid = threadIdx.x;
    const int blk = blockIdx.x;
    const int gc0 = blk * 8;              // 8 gate-cols per block
    const int grp = tid >> 6;             // k-split group 0..3
    const int gt  = tid & 63;
    const int rowg = gt >> 2;             // 16 row groups of 4
    const int cg   = gt & 3;              // 4 col groups of 6

    // ---- load W slice into smem once: w_s[k][p*8 + half*4 + 0..3] ----------
#pragma unroll
    for (int j = 0; j < 24; j++) {
        int l = tid + j * 256;            // 0..6143 float4s
        int k = l / 6, f = l - k * 6;
        int p = f >> 1, half = f & 1;
        const float* src = (p == 0) ? (W1 + (size_t)k * 2048 + gc0 + half * 4)
                         : (p == 1) ? (W1 + (size_t)k * 2048 + 1024 + gc0 + half * 4)
                                    : (W2 + (size_t)k * 1024 + gc0 + half * 4);
        *(float4*)&w_s[k * 24 + p * 8 + half * 4] = *(const float4*)src;
    }
    if (tid < 24) {
        int p = tid >> 3, ii = tid & 7, n = gc0 + ii;
        bias_s[tid] = (p == 0) ? b1[n] : (p == 1) ? b1[1024 + n] : b2[n];
    }
    __syncthreads();

    for (int t = 0; t < Tt; t++) {
        const float* hcur = g_Ht[t & 1];
        float*       hnxt = g_Ht[(t + 1) & 1];

        // ---- prefetch gating inputs (arrive during GEMM) -------------------
        float xq[2][3], hp[2];
#pragma unroll
        for (int e = 0; e < 2; e++) {
            int idx = tid + e * 256;              // 0..511
            int m = idx & 63, i = idx >> 6;
            int n = gc0 + i;
            const float* xp = g_XP + ((size_t)(m * Tt + t)) * N3 + n;
            xq[e][0] = xp[0];
            xq[e][1] = xp[1024];
            xq[e][2] = xp[2048];
            hp[e]    = hcur[n * 64 + m];
        }

        // ---- GEMM: 24 cols x 64 rows, full K, 4-way in-block K split -------
        ull acc[4][3];
#pragma unroll
        for (int i = 0; i < 4; i++) { acc[i][0] = 0; acc[i][1] = 0; acc[i][2] = 0; }

        for (int it = 0; it < 4; it++) {
            // coop load: each group's 64-k sub-chunk, transposed, coalesced
#pragma unroll
            for (int j = 0; j < 16; j++) {
                int l = tid + j * 256;            // 0..4095 float4s
                int m4 = l & 15, kl = (l >> 4) & 63, g = l >> 10;
                *(float4*)&hT_s[(g * 64 + kl) * 64 + m4 * 4] =
                    *(const float4*)&hcur[(g * 256 + it * 64 + kl) * 64 + m4 * 4];
            }
            __syncthreads();

            const float* hg = hT_s + grp * (64 * 64);
            const float* wb = w_s + (grp * 256 + it * 64) * 24;
#pragma unroll 8
            for (int kk = 0; kk < 64; kk++) {
                float4 hv = *(const float4*)&hg[kk * 64 + rowg * 4];
                const ull* wv = (const ull*)&wb[kk * 24 + cg * 6];
                const ull w0 = wv[0], w1 = wv[1], w2 = wv[2];
                float ar[4] = {hv.x, hv.y, hv.z, hv.w};
#pragma unroll
                for (int i = 0; i < 4; i++) {
                    ull aa = pk2(ar[i], ar[i]);
                    ffma2(acc[i][0], aa, w0);
                    ffma2(acc[i][1], aa, w1);
                    ffma2(acc[i][2], aa, w2);
                }
            }
            __syncthreads();
        }

        // ---- write in-block partials --------------------------------------
#pragma unroll
        for (int i = 0; i < 4; i++) {
            ull* pp = (ull*)&p_s[(grp * 64 + rowg * 4 + i) * 26 + cg * 6];
            pp[0] = acc[i][0]; pp[1] = acc[i][1]; pp[2] = acc[i][2];
        }
        __syncthreads();

        // ---- fused reduce + gates + h update (block-local) -----------------
#pragma unroll
        for (int e = 0; e < 2; e++) {
            int idx = tid + e * 256;
            int m = idx & 63, i = idx >> 6;
            int n = gc0 + i;
            float s1 = 0.f, s2 = 0.f, sh = 0.f;
#pragma unroll
            for (int g = 0; g < 4; g++) {
                const float* pp = &p_s[(g * 64 + m) * 26];
                s1 += pp[i]; s2 += pp[8 + i]; sh += pp[16 + i];
            }
            // reference adds biases in BOTH x-proj and h-proj — replicate
            float z = 1.f / (1.f + expf(-(xq[e][0] + s1 + bias_s[i])));
            float r = 1.f / (1.f + expf(-(xq[e][1] + s2 + bias_s[8 + i])));
            float hrec = sh + bias_s[16 + i];
            float hn = z * hp[e] + (1.f - z) * tanhf(xq[e][2] + r * hrec);
            hnxt[n * 64 + m] = hn;                 // transposed, coalesced
            if (t == Tt - 1) out[m * Nn + n] = hn;
        }

        __threadfence();
        grid_sync();   // single barrier: h[next] visible before next step reads
    }
}

// ---------------------------------------------------------------------------
extern "C" void kernel_launch(void* const* d_in, const int* in_sizes, int n_in,
                              void* d_out, int out_size) {
    const float *fx = nullptr, *W1 = nullptr, *b1 = nullptr, *W2 = nullptr, *b2 = nullptr;
    for (int i = 0; i < n_in; i++) {
        switch (in_sizes[i]) {
            case Bsz * Nn * Tt:  fx = (const float*)d_in[i]; break;
            case Nn * 2 * Nn:    W1 = (const float*)d_in[i]; break;
            case 2 * Nn:         b1 = (const float*)d_in[i]; break;
            case Nn * Nn:        W2 = (const float*)d_in[i]; break;
            case Nn:             b2 = (const float*)d_in[i]; break;
            default: break;
        }
    }
    float* out = (float*)d_out;

    static int smem_set = 0;
    if (!smem_set) {
        cudaFuncSetAttribute(recurrence, cudaFuncAttributeMaxDynamicSharedMemorySize,
                             SM_TOT);
        smem_set = 1;
    }

    pack_w<<<(Kd * N3 + 255) / 256, 256>>>(W1, b1, W2, b2);
    init_state<<<(Nn * Bsz + 255) / 256, 256>>>();

    dim3 g1(N3 / 128, (Bsz * Tt) / 128);   // (24, 256)
    xproj<<<g1, 256>>>(fx);

    recurrence<<<NB, 256, SM_TOT>>>(W1, W2, b1, b2, out);
}

// round 9
// speedup vs baseline: 1.1162x; 1.0395x over previous
#include <cuda_runtime.h>
#include <cuda_bf16.h>
#include <cstddef>

// ---------------------------------------------------------------------------
// GRU (B=64, N=1024, T=512), exact fp32, packed f32x2 FMA.
//
// Phase 1:  XP = x @ [W1|W2] + [b1|b2] — double-buffered BK=16 SGEMM,
//           2 CTAs/SM, one sync per chunk, prefetch overlapped with compute.
// Phase 2:  ONE persistent kernel (unchanged from R7): 128 blocks, W resident
//           in smem, transposed double-buffered h, one grid barrier per step.
// ---------------------------------------------------------------------------

#define Bsz 64
#define Nn  1024
#define Tt  512
#define N3  3072
#define Kd  1024
#define NB  128

typedef unsigned long long ull;

__device__ __forceinline__ ull pk2(float lo, float hi) {
    ull r; asm("mov.b64 %0, {%1,%2};" : "=l"(r) : "f"(lo), "f"(hi)); return r;
}
__device__ __forceinline__ void upk2(ull v, float& lo, float& hi) {
    asm("mov.b64 {%0,%1}, %2;" : "=f"(lo), "=f"(hi) : "l"(v));
}
__device__ __forceinline__ void ffma2(ull& d, ull a, ull b) {
    asm("fma.rn.f32x2 %0, %1, %2, %0;" : "+l"(d) : "l"(a), "l"(b));
}

// ------------------------- device scratch ----------------------------------
__device__ float g_Wc[(size_t)Kd * N3];          // 12 MB packed [W1|W2]
__device__ float g_bc[N3];
__device__ float g_XP[(size_t)Bsz * Tt * N3];    // 402 MB input projections
__device__ float g_Ht[2][(size_t)Nn * Bsz];      // h, TRANSPOSED [k][m]

__device__ volatile unsigned g_bar_gen;
__device__ unsigned g_bar_cnt;

// ------------------------- init / pack -------------------------------------
__global__ void pack_w(const float* __restrict__ W1, const float* __restrict__ b1,
                       const float* __restrict__ W2, const float* __restrict__ b2) {
    int idx = blockIdx.x * 256 + threadIdx.x;
    if (idx < Kd * N3) {
        int k = idx / N3, j = idx - k * N3;
        g_Wc[idx] = (j < 2048) ? W1[k * 2048 + j] : W2[k * 1024 + (j - 2048)];
    }
    if (idx < N3) g_bc[idx] = (idx < 2048) ? b1[idx] : b2[idx - 2048];
}

__global__ void init_state() {
    int i = blockIdx.x * 256 + threadIdx.x;
    if (i < Nn * Bsz) g_Ht[0][i] = 0.f;
    if (i == 0) { g_bar_cnt = 0; g_bar_gen = 0; }
}

// ------------------------- phase 1: input projection ------------------------
// C[32768, 3072] = A[32768,1024] * Wc + bc.
// BM=BN=128, BK=16, 256 threads, 8x8/thread, ping-pong double buffer.
__global__ __launch_bounds__(256, 2) void xproj(const float* __restrict__ fx) {
    __shared__ float As[2][16][128];
    __shared__ float Bs[2][16][128];

    const int tid = threadIdx.x;
    const int jb  = blockIdx.x * 128;
    const int m0  = blockIdx.y * 128;
    const int b   = m0 >> 9;
    const int t0  = m0 & 511;
    const float* Abase = fx + ((size_t)b * Kd) * Tt + t0;

    const int lm = tid & 31;          // float4 index along m / j (0..31)
    const int lk = tid >> 5;          // k row 0..7 (+8 for second pass)
    const int ty = tid >> 4, tx = tid & 15;

    float4 ar[2], br[2];
#pragma unroll
    for (int i = 0; i < 2; i++) {
        int k = lk + i * 8;
        ar[i] = *(const float4*)(Abase + (size_t)k * Tt + lm * 4);
        br[i] = *(const float4*)(g_Wc + (size_t)k * N3 + jb + lm * 4);
    }
#pragma unroll
    for (int i = 0; i < 2; i++) {
        int k = lk + i * 8;
        *(float4*)&As[0][k][lm * 4] = ar[i];
        *(float4*)&Bs[0][k][lm * 4] = br[i];
    }
    __syncthreads();

    ull acc[8][4];
#pragma unroll
    for (int r = 0; r < 8; r++)
#pragma unroll
        for (int c = 0; c < 4; c++) acc[r][c] = 0ull;

    int buf = 0;
    for (int k0 = 0; k0 < Kd; k0 += 16) {
        const bool more = (k0 + 16 < Kd);
        if (more) {
#pragma unroll
            for (int i = 0; i < 2; i++) {
                int k = k0 + 16 + lk + i * 8;
                ar[i] = *(const float4*)(Abase + (size_t)k * Tt + lm * 4);
                br[i] = *(const float4*)(g_Wc + (size_t)k * N3 + jb + lm * 4);
            }
        }

#pragma unroll
        for (int q = 0; q < 16; q++) {
            const float4 a0 = *(const float4*)&As[buf][q][ty * 8];
            const float4 a1 = *(const float4*)&As[buf][q][ty * 8 + 4];
            const float4 bl = *(const float4*)&Bs[buf][q][tx * 8];
            const float4 bh = *(const float4*)&Bs[buf][q][tx * 8 + 4];
            const ull b0 = pk2(bl.x, bl.y), b1v = pk2(bl.z, bl.w);
            const ull b2v = pk2(bh.x, bh.y), b3v = pk2(bh.z, bh.w);
            float arow[8] = {a0.x, a0.y, a0.z, a0.w, a1.x, a1.y, a1.z, a1.w};
#pragma unroll
            for (int r = 0; r < 8; r++) {
                ull aa = pk2(arow[r], arow[r]);
                ffma2(acc[r][0], aa, b0);
                ffma2(acc[r][1], aa, b1v);
                ffma2(acc[r][2], aa, b2v);
                ffma2(acc[r][3], aa, b3v);
            }
        }

        if (more) {
            int nb = buf ^ 1;
#pragma unroll
            for (int i = 0; i < 2; i++) {
                int k = lk + i * 8;
                *(float4*)&As[nb][k][lm * 4] = ar[i];
                *(float4*)&Bs[nb][k][lm * 4] = br[i];
            }
        }
        __syncthreads();
        buf ^= 1;
    }

    float bb[8];
#pragma unroll
    for (int c = 0; c < 8; c++) bb[c] = g_bc[jb + tx * 8 + c];

#pragma unroll
    for (int r = 0; r < 8; r++) {
        float* op = g_XP + (size_t)(m0 + ty * 8 + r) * N3 + jb + tx * 8;
        float4 v0, v1;
        upk2(acc[r][0], v0.x, v0.y); upk2(acc[r][1], v0.z, v0.w);
        upk2(acc[r][2], v1.x, v1.y); upk2(acc[r][3], v1.z, v1.w);
        v0.x += bb[0]; v0.y += bb[1]; v0.z += bb[2]; v0.w += bb[3];
        v1.x += bb[4]; v1.y += bb[5]; v1.z += bb[6]; v1.w += bb[7];
        *(float4*)&op[0] = v0;
        *(float4*)&op[4] = v1;
    }
}

// ------------------------- phase 2: persistent recurrence (R7, unchanged) ---
#define SM_W   (1024 * 24)
#define SM_HT  (4 * 64 * 64)
#define SM_P   (4 * 64 * 26)
#define SM_TOT ((SM_W + SM_HT + SM_P + 24) * 4)

__device__ __forceinline__ void grid_sync() {
    __syncthreads();
    if (threadIdx.x == 0) {
        unsigned gen = g_bar_gen;
        __threadfence();
        if (atomicAdd(&g_bar_cnt, 1u) == NB - 1) {
            g_bar_cnt = 0;
            __threadfence();
            g_bar_gen = gen + 1;
        } else {
            while (g_bar_gen == gen) { __nanosleep(64); }
        }
        __threadfence();
    }
    __syncthreads();
}

__global__ __launch_bounds__(256, 1) void recurrence(
        const float* __restrict__ W1, const float* __restrict__ W2,
        const float* __restrict__ b1, const float* __restrict__ b2,
        float* __restrict__ out) {
    extern __shared__ float smem[];
    float* w_s    = smem;                 // [k][24]
    float* hT_s   = w_s + SM_W;           // [g][64][64]
    float* p_s    = hT_s + SM_HT;         // [g][64][26]
    float* bias_s = p_s + SM_P;           // [24]

    const int tid = threadIdx.x;
    const int blk = blockIdx.x;
    const int gc0 = blk * 8;
    const int grp = tid >> 6;
    const int gt  = tid & 63;
    const int rowg = gt >> 2;
    const int cg   = gt & 3;

#pragma unroll
    for (int j = 0; j < 24; j++) {
        int l = tid + j * 256;
        int k = l / 6, f = l - k * 6;
        int p = f >> 1, half = f & 1;
        const float* src = (p == 0) ? (W1 + (size_t)k * 2048 + gc0 + half * 4)
                         : (p == 1) ? (W1 + (size_t)k * 2048 + 1024 + gc0 + half * 4)
                                    : (W2 + (size_t)k * 1024 + gc0 + half * 4);
        *(float4*)&w_s[k * 24 + p * 8 + half * 4] = *(const float4*)src;
    }
    if (tid < 24) {
        int p = tid >> 3, ii = tid & 7, n = gc0 + ii;
        bias_s[tid] = (p == 0) ? b1[n] : (p == 1) ? b1[1024 + n] : b2[n];
    }
    __syncthreads();

    for (int t = 0; t < Tt; t++) {
        const float* hcur = g_Ht[t & 1];
        float*       hnxt = g_Ht[(t + 1) & 1];

        float xq[2][3], hp[2];
#pragma unroll
        for (int e = 0; e < 2; e++) {
            int idx = tid + e * 256;
            int m = idx & 63, i = idx >> 6;
            int n = gc0 + i;
            const float* xp = g_XP + ((size_t)(m * Tt + t)) * N3 + n;
            xq[e][0] = xp[0];
            xq[e][1] = xp[1024];
            xq[e][2] = xp[2048];
            hp[e]    = hcur[n * 64 + m];
        }

        ull acc[4][3];
#pragma unroll
        for (int i = 0; i < 4; i++) { acc[i][0] = 0; acc[i][1] = 0; acc[i][2] = 0; }

        for (int it = 0; it < 4; it++) {
#pragma unroll
            for (int j = 0; j < 16; j++) {
                int l = tid + j * 256;
                int m4 = l & 15, kl = (l >> 4) & 63, g = l >> 10;
                *(float4*)&hT_s[(g * 64 + kl) * 64 + m4 * 4] =
                    *(const float4*)&hcur[(g * 256 + it * 64 + kl) * 64 + m4 * 4];
            }
            __syncthreads();

            const float* hg = hT_s + grp * (64 * 64);
            const float* wb = w_s + (grp * 256 + it * 64) * 24;
#pragma unroll 8
            for (int kk = 0; kk < 64; kk++) {
                float4 hv = *(const float4*)&hg[kk * 64 + rowg * 4];
                const ull* wv = (const ull*)&wb[kk * 24 + cg * 6];
                const ull w0 = wv[0], w1 = wv[1], w2 = wv[2];
                float arv[4] = {hv.x, hv.y, hv.z, hv.w};
#pragma unroll
                for (int i = 0; i < 4; i++) {
                    ull aa = pk2(arv[i], arv[i]);
                    ffma2(acc[i][0], aa, w0);
                    ffma2(acc[i][1], aa, w1);
                    ffma2(acc[i][2], aa, w2);
                }
            }
            __syncthreads();
        }

#pragma unroll
        for (int i = 0; i < 4; i++) {
            ull* pp = (ull*)&p_s[(grp * 64 + rowg * 4 + i) * 26 + cg * 6];
            pp[0] = acc[i][0]; pp[1] = acc[i][1]; pp[2] = acc[i][2];
        }
        __syncthreads();

#pragma unroll
        for (int e = 0; e < 2; e++) {
            int idx = tid + e * 256;
            int m = idx & 63, i = idx >> 6;
            int n = gc0 + i;
            float s1 = 0.f, s2 = 0.f, sh = 0.f;
#pragma unroll
            for (int g = 0; g < 4; g++) {
                const float* pp = &p_s[(g * 64 + m) * 26];
                s1 += pp[i]; s2 += pp[8 + i]; sh += pp[16 + i];
            }
            float z = 1.f / (1.f + expf(-(xq[e][0] + s1 + bias_s[i])));
            float r = 1.f / (1.f + expf(-(xq[e][1] + s2 + bias_s[8 + i])));
            float hrec = sh + bias_s[16 + i];
            float hn = z * hp[e] + (1.f - z) * tanhf(xq[e][2] + r * hrec);
            hnxt[n * 64 + m] = hn;
            if (t == Tt - 1) out[m * Nn + n] = hn;
        }

        __threadfence();
        grid_sync();
    }
}

// ---------------------------------------------------------------------------
extern "C" void kernel_launch(void* const* d_in, const int* in_sizes, int n_in,
                              void* d_out, int out_size) {
    const float *fx = nullptr, *W1 = nullptr, *b1 = nullptr, *W2 = nullptr, *b2 = nullptr;
    for (int i = 0; i < n_in; i++) {
        switch (in_sizes[i]) {
            case Bsz * Nn * Tt:  fx = (const float*)d_in[i]; break;
            case Nn * 2 * Nn:    W1 = (const float*)d_in[i]; break;
            case 2 * Nn:         b1 = (const float*)d_in[i]; break;
            case Nn * Nn:        W2 = (const float*)d_in[i]; break;
            case Nn:             b2 = (const float*)d_in[i]; break;
            default: break;
        }
    }
    float* out = (float*)d_out;

    static int smem_set = 0;
    if (!smem_set) {
        cudaFuncSetAttribute(recurrence, cudaFuncAttributeMaxDynamicSharedMemorySize,
                             SM_TOT);
        smem_set = 1;
    }

    pack_w<<<(Kd * N3 + 255) / 256, 256>>>(W1, b1, W2, b2);
    init_state<<<(Nn * Bsz + 255) / 256, 256>>>();

    dim3 g1(N3 / 128, (Bsz * Tt) / 128);   // (24, 256)
    xproj<<<g1, 256>>>(fx);

    recurrence<<<NB, 256, SM_TOT>>>(W1, W2, b1, b2, out);
}